// round 6
// baseline (speedup 1.0000x reference)
#include <cuda_runtime.h>
#include <math.h>

#define BB   64
#define SS   512
#define II   512
#define HH   1024
#define G4   4096
#define OO   512
#define BH   (BB*HH)          // 65536
#define OUT_ELEMS (BB*SS*OO)  // 16777216
#define NBLK 128

typedef unsigned long long u64;

// -------- scratch (device globals; allocation-free per rules) --------
__device__ float g_xg[(size_t)SS * BB * G4];   // 512 MB, reused for both layers
__device__ float g_y [(size_t)BB * SS * HH];   // 128 MB, y0 then y1 (in place)
__device__ float g_h [2 * BH + 64];            // double-buffered hidden state
__device__ unsigned g_bar;                     // grid barrier counter

// ---------------- f32x2 helpers (sm_103a packed fp32 pipe) ----------------
__device__ __forceinline__ void fma2(u64& d, u64 a, u64 b) {
    asm("fma.rn.f32x2 %0, %1, %2, %3;" : "=l"(d) : "l"(a), "l"(b), "l"(d));
}
__device__ __forceinline__ u64 splat2(float v) {
    u64 r; asm("mov.b64 %0, {%1, %1};" : "=l"(r) : "f"(v)); return r;
}
__device__ __forceinline__ float2 unpack2(u64 a) {
    float2 r; asm("mov.b64 {%0, %1}, %2;" : "=f"(r.x), "=f"(r.y) : "l"(a)); return r;
}
__device__ __forceinline__ float fast_sig(float x) {
    return __fdividef(1.f, 1.f + __expf(-x));
}
__device__ __forceinline__ float fast_tanh(float x) {
    return 2.f * fast_sig(2.f * x) - 1.f;
}

// ---------------------------------------------------------------
// Tiled fp32 GEMM with f32x2 inner product (pack along row pairs).
// ---------------------------------------------------------------
__global__ __launch_bounds__(256, 2)
void gemm_kernel(const float* __restrict__ A, const float* __restrict__ W,
                 const float* __restrict__ ba, const float* __restrict__ bb,
                 float* __restrict__ C, int M, int N, int K, int mapA)
{
    __shared__ float As[16][132];
    __shared__ float Ws[16][132];

    const int tid = threadIdx.x;
    const int bm  = blockIdx.y * 128;
    const int bn  = blockIdx.x * 128;
    const int tx  = tid & 15;
    const int ty  = tid >> 4;
    const int row0  = ty * 8;
    const int col0a = tx * 4;
    const int col0b = 64 + tx * 4;

    const int idx0 = tid * 2;
    const int idx1 = tid * 2 + 1;
    const int lrA0 = idx0 >> 2, kqA0 = idx0 & 3;
    const int lrA1 = idx1 >> 2, kqA1 = idx1 & 3;

    int m0 = bm + lrA0, m1 = bm + lrA1;
    long ar0 = mapA ? ((long)(m0 & 63) * SS + (m0 >> 6)) : (long)m0;
    long ar1 = mapA ? ((long)(m1 & 63) * SS + (m1 >> 6)) : (long)m1;
    const float* Ap0 = A + ar0 * K;
    const float* Ap1 = A + ar1 * K;
    const float* Wp0 = W + (long)(bn + lrA0) * K;
    const float* Wp1 = W + (long)(bn + lrA1) * K;

    u64 acc2[4][8];
#pragma unroll
    for (int i = 0; i < 4; i++)
#pragma unroll
        for (int j = 0; j < 8; j++) acc2[i][j] = 0ull;

    for (int k0 = 0; k0 < K; k0 += 16) {
        float4 av0 = *(const float4*)(Ap0 + k0 + kqA0 * 4);
        float4 av1 = *(const float4*)(Ap1 + k0 + kqA1 * 4);
        float4 wv0 = *(const float4*)(Wp0 + k0 + kqA0 * 4);
        float4 wv1 = *(const float4*)(Wp1 + k0 + kqA1 * 4);

        __syncthreads();
        As[kqA0*4+0][lrA0] = av0.x; As[kqA0*4+1][lrA0] = av0.y;
        As[kqA0*4+2][lrA0] = av0.z; As[kqA0*4+3][lrA0] = av0.w;
        As[kqA1*4+0][lrA1] = av1.x; As[kqA1*4+1][lrA1] = av1.y;
        As[kqA1*4+2][lrA1] = av1.z; As[kqA1*4+3][lrA1] = av1.w;
        Ws[kqA0*4+0][lrA0] = wv0.x; Ws[kqA0*4+1][lrA0] = wv0.y;
        Ws[kqA0*4+2][lrA0] = wv0.z; Ws[kqA0*4+3][lrA0] = wv0.w;
        Ws[kqA1*4+0][lrA1] = wv1.x; Ws[kqA1*4+1][lrA1] = wv1.y;
        Ws[kqA1*4+2][lrA1] = wv1.z; Ws[kqA1*4+3][lrA1] = wv1.w;
        __syncthreads();

#pragma unroll
        for (int k = 0; k < 16; k++) {
            ulonglong2 a01 = *(const ulonglong2*)&As[k][row0];
            ulonglong2 a23 = *(const ulonglong2*)&As[k][row0 + 4];
            float4 bA = *(const float4*)&Ws[k][col0a];
            float4 bB = *(const float4*)&Ws[k][col0b];
            u64 a2[4] = {a01.x, a01.y, a23.x, a23.y};
            u64 w2[8];
            w2[0] = splat2(bA.x); w2[1] = splat2(bA.y);
            w2[2] = splat2(bA.z); w2[3] = splat2(bA.w);
            w2[4] = splat2(bB.x); w2[5] = splat2(bB.y);
            w2[6] = splat2(bB.z); w2[7] = splat2(bB.w);
#pragma unroll
            for (int i = 0; i < 4; i++)
#pragma unroll
                for (int j = 0; j < 8; j++)
                    fma2(acc2[i][j], a2[i], w2[j]);
        }
    }

    float biasA[4], biasB[4];
#pragma unroll
    for (int j = 0; j < 4; j++) {
        int na = bn + col0a + j, nb = bn + col0b + j;
        biasA[j] = ba[na] + (bb ? bb[na] : 0.f);
        biasB[j] = ba[nb] + (bb ? bb[nb] : 0.f);
    }
#pragma unroll
    for (int i = 0; i < 4; i++) {
        long mA = bm + row0 + 2 * i;
        long mB = mA + 1;
        float2 u[8];
#pragma unroll
        for (int j = 0; j < 8; j++) u[j] = unpack2(acc2[i][j]);
        float4 oA0 = {u[0].x + biasA[0], u[1].x + biasA[1], u[2].x + biasA[2], u[3].x + biasA[3]};
        float4 oA1 = {u[4].x + biasB[0], u[5].x + biasB[1], u[6].x + biasB[2], u[7].x + biasB[3]};
        float4 oB0 = {u[0].y + biasA[0], u[1].y + biasA[1], u[2].y + biasA[2], u[3].y + biasA[3]};
        float4 oB1 = {u[4].y + biasB[0], u[5].y + biasB[1], u[6].y + biasB[2], u[7].y + biasB[3]};
        *(float4*)&C[mA * N + bn + col0a] = oA0;
        *(float4*)&C[mA * N + bn + col0b] = oA1;
        *(float4*)&C[mB * N + bn + col0a] = oB0;
        *(float4*)&C[mB * N + bn + col0b] = oB1;
    }
}

// ---------------------------------------------------------------
// Persistent LSTM layer kernel. 128 blocks, 256 threads, 512 steps.
// W_hh (32x1024) in XOR-swizzled smem. h staged through smem in 8 chunks
// of 128 floats/row with register prefetch (8 LDG.128/thread/chunk).
// Hs row stride = 33 float4 (conflict-free). All math packed f32x2.
// smem: W 128KB + Hs 33.8KB + Pm 8.4KB + Cs 2KB = 175,360 B
// ---------------------------------------------------------------
__global__ __launch_bounds__(256, 1)
void lstm_layer_kernel(const float* __restrict__ xg,    // [S][64][4096]
                       const float* __restrict__ Whh,   // [4096][1024]
                       float* __restrict__ h,           // [2][64][1024]
                       float* __restrict__ y,           // [B][S][H]
                       float* __restrict__ out_h,
                       float* __restrict__ out_c)
{
    extern __shared__ float smem[];
    float* Wall = smem;                          // 32*1024 floats, swizzled
    float* HsF  = smem + 32 * 1024;              // 64 rows * 33 float4 = 8448 floats
    float* Pm   = HsF + 64 * 132;                // 64*33
    float* Cs   = Pm + 64 * 33;                  // 512

    float4*     Hs4 = (float4*)HsF;
    ulonglong2* HsU = (ulonglong2*)HsF;

    const int tid = threadIdx.x;
    const int j0  = blockIdx.x * 8;
    const int tx  = tid & 15;
    const int ty  = tid >> 4;
    const int c0  = tx * 2;
    const int r0  = ty * 4;
    const int swz = tx & 7;

    // staging map: 2048 float4 per chunk-set? chunk = 64 rows x 32 float4 = 2048 f4
    // per thread 8: idx = i*256 + tid; row = idx>>5, kc = idx&31
    int soff[8];   // gmem float offset within h_in (row*HH + kc*4), chunk adds cc*128
    int sslot[8];  // smem float4 slot (row*33 + kc)
#pragma unroll
    for (int i = 0; i < 8; i++) {
        int idx = i * 256 + tid;
        int row = idx >> 5, kc = idx & 31;
        soff[i]  = row * HH + kc * 4;
        sslot[i] = row * 33 + kc;
    }

    // ---- prologue: zero h (both buffers), Cs; load swizzled W tile ----
    {
        float4 z = make_float4(0.f, 0.f, 0.f, 0.f);
        *(float4*)&h[blockIdx.x * 1024 + tid * 4] = z;
        Cs[tid]       = 0.f;
        Cs[tid + 256] = 0.f;
    }
#pragma unroll 4
    for (int i = 0; i < 32; i++) {
        int idx = i * 256 + tid;
        int wr = idx >> 8;
        int kq = idx & 255;
        int grow = (wr >> 3) * HH + j0 + (wr & 7);
        float4 v = *(const float4*)(Whh + (long)grow * HH + kq * 4);
        int slot = kq ^ ((wr >> 1) & 7);
        *(float4*)&Wall[wr * 1024 + slot * 4] = v;
    }

    unsigned nbar = 0;
    __syncthreads();
    nbar++;
    if (tid == 0) {
        __threadfence();
        atomicAdd(&g_bar, 1u);
        while (*(volatile unsigned*)&g_bar < nbar * NBLK) { }
    }
    __syncthreads();

    const ulonglong2* Wp0 = (const ulonglong2*)&Wall[c0 * 1024];
    const ulonglong2* Wp1 = (const ulonglong2*)&Wall[(c0 + 1) * 1024];

    for (int t = 0; t < SS; t++) {
        const float* h_in  = h + (size_t)(t & 1) * BH;
        float*       h_out = h + (size_t)((t + 1) & 1) * BH;
        const float* xg_t  = xg + (size_t)t * BB * G4;

        // xg contribution for this thread's 4x2 micro-tile
        const int gate = c0 >> 3;
        const int jl0  = c0 & 7;
        float2 xv[4];
#pragma unroll
        for (int r = 0; r < 4; r++)
            xv[r] = *(const float2*)(xg_t + (long)(r0 + r) * G4 + gate * HH + j0 + jl0);

        u64 acc[4][2];
#pragma unroll
        for (int r = 0; r < 4; r++) { acc[r][0] = 0ull; acc[r][1] = 0ull; }

        // prefetch chunk 0
        float4 pf[8];
#pragma unroll
        for (int i = 0; i < 8; i++)
            pf[i] = __ldcg((const float4*)(h_in + soff[i]));

#pragma unroll 1
        for (int cc = 0; cc < 8; cc++) {
            __syncthreads();           // previous chunk fully consumed
#pragma unroll
            for (int i = 0; i < 8; i++) Hs4[sslot[i]] = pf[i];
            __syncthreads();
            if (cc < 7) {
#pragma unroll
                for (int i = 0; i < 8; i++)
                    pf[i] = __ldcg((const float4*)(h_in + soff[i] + (cc + 1) * 128));
            }

            const int kqb = cc * 32;
#pragma unroll 4
            for (int kql = 0; kql < 32; kql++) {
                int s = (kqb + kql) ^ swz;
                ulonglong2 w0 = Wp0[s];
                ulonglong2 w1 = Wp1[s];
#pragma unroll
                for (int r = 0; r < 4; r++) {
                    ulonglong2 hv = HsU[(r0 + r) * 33 + kql];
                    fma2(acc[r][0], hv.x, w0.x);
                    fma2(acc[r][0], hv.y, w0.y);
                    fma2(acc[r][1], hv.x, w1.x);
                    fma2(acc[r][1], hv.y, w1.y);
                }
            }
        }

        // fold lo+hi, add xg, stash pre-activations
#pragma unroll
        for (int r = 0; r < 4; r++) {
            int b = r0 + r;
            float2 u0 = unpack2(acc[r][0]);
            float2 u1 = unpack2(acc[r][1]);
            Pm[b * 33 + c0]     = u0.x + u0.y + xv[r].x;
            Pm[b * 33 + c0 + 1] = u1.x + u1.y + xv[r].y;
        }
        __syncthreads();

        // gate math: 512 (b, jl) pairs, 2 per thread
#pragma unroll
        for (int pi = 0; pi < 2; pi++) {
            int p  = tid + pi * 256;
            int b  = p >> 3;
            int jl = p & 7;
            int j  = j0 + jl;
            float iv = fast_sig (Pm[b * 33 + 0  + jl]);
            float fv = fast_sig (Pm[b * 33 + 8  + jl]);
            float gv = fast_tanh(Pm[b * 33 + 16 + jl]);
            float ov = fast_sig (Pm[b * 33 + 24 + jl]);
            float cn = fv * Cs[b * 8 + jl] + iv * gv;
            Cs[b * 8 + jl] = cn;
            float hn = ov * fast_tanh(cn);
            __stcg(h_out + (long)b * HH + j, hn);
            y[((long)b * SS + t) * HH + j] = hn;
            if (t == SS - 1) {
                out_h[(long)b * HH + j] = hn;
                out_c[(long)b * HH + j] = cn;
            }
        }

        // grid barrier: everyone's h_out visible before next step reads it
        __threadfence();
        __syncthreads();
        nbar++;
        if (tid == 0) {
            atomicAdd(&g_bar, 1u);
            while (*(volatile unsigned*)&g_bar < nbar * NBLK) { }
            __threadfence();
        }
        __syncthreads();
    }
}

extern "C" void kernel_launch(void* const* d_in, const int* in_sizes, int n_in,
                              void* d_out, int out_size)
{
    const float* x     = (const float*)d_in[0];
    const float* W_ih0 = (const float*)d_in[1];
    const float* W_hh0 = (const float*)d_in[2];
    const float* b_ih0 = (const float*)d_in[3];
    const float* b_hh0 = (const float*)d_in[4];
    const float* W_ih1 = (const float*)d_in[5];
    const float* W_hh1 = (const float*)d_in[6];
    const float* b_ih1 = (const float*)d_in[7];
    const float* b_hh1 = (const float*)d_in[8];
    const float* W_fc  = (const float*)d_in[9];
    const float* b_fc  = (const float*)d_in[10];
    float* out = (float*)d_out;

    float *xg, *y, *h;
    unsigned* bar;
    cudaGetSymbolAddress((void**)&xg,  g_xg);
    cudaGetSymbolAddress((void**)&y,   g_y);
    cudaGetSymbolAddress((void**)&h,   g_h);
    cudaGetSymbolAddress((void**)&bar, g_bar);

    const int SMEM_LAYER = (32 * 1024 + 64 * 132 + 64 * 33 + 512) * 4;  // 175,360
    cudaFuncSetAttribute(lstm_layer_kernel,
                         cudaFuncAttributeMaxDynamicSharedMemorySize, SMEM_LAYER);

    const int M = SS * BB;  // 32768

    // ---------------- layer 0 ----------------
    gemm_kernel<<<dim3(G4 / 128, M / 128), 256>>>(
        x, W_ih0, b_ih0, b_hh0, xg, M, G4, II, 1);
    cudaMemsetAsync(bar, 0, sizeof(unsigned));
    lstm_layer_kernel<<<NBLK, 256, SMEM_LAYER>>>(
        xg, W_hh0, h, y,
        out + OUT_ELEMS,
        out + OUT_ELEMS + 2 * BH);

    // ---------------- layer 1 ----------------
    gemm_kernel<<<dim3(G4 / 128, M / 128), 256>>>(
        y, W_ih1, b_ih1, b_hh1, xg, M, G4, HH, 1);
    cudaMemsetAsync(bar, 0, sizeof(unsigned));
    lstm_layer_kernel<<<NBLK, 256, SMEM_LAYER>>>(
        xg, W_hh1, h, y,
        out + OUT_ELEMS + BH,
        out + OUT_ELEMS + 3 * BH);

    // ---------------- FC ----------------
    gemm_kernel<<<dim3(OO / 128, M / 128), 256>>>(
        y, W_fc, b_fc, nullptr, out, M, OO, HH, 0);
}

// round 7
// speedup vs baseline: 1.0359x; 1.0359x over previous
#include <cuda_runtime.h>
#include <math.h>

#define BB   64
#define SS   512
#define II   512
#define HH   1024
#define G4   4096
#define OO   512
#define BH   (BB*HH)          // 65536
#define OUT_ELEMS (BB*SS*OO)  // 16777216
#define NBLK 128

typedef unsigned long long u64;

// -------- scratch (device globals; allocation-free per rules) --------
__device__ float g_xg[(size_t)SS * BB * G4];   // 512 MB, reused for both layers
__device__ float g_y [(size_t)BB * SS * HH];   // 128 MB, y0 then y1 (in place)
__device__ float g_h [2 * BH + 64];            // double-buffered hidden state
__device__ unsigned g_bar;                     // grid barrier counter

// ---------------- f32x2 helpers (sm_103a packed fp32 pipe) ----------------
__device__ __forceinline__ void fma2(u64& d, u64 a, u64 b) {
    asm("fma.rn.f32x2 %0, %1, %2, %3;" : "=l"(d) : "l"(a), "l"(b), "l"(d));
}
__device__ __forceinline__ u64 splat2(float v) {
    u64 r; asm("mov.b64 %0, {%1, %1};" : "=l"(r) : "f"(v)); return r;
}
__device__ __forceinline__ float2 unpack2(u64 a) {
    float2 r; asm("mov.b64 {%0, %1}, %2;" : "=f"(r.x), "=f"(r.y) : "l"(a)); return r;
}
__device__ __forceinline__ float fast_sig(float x) {
    return __fdividef(1.f, 1.f + __expf(-x));
}
__device__ __forceinline__ float fast_tanh(float x) {
    return 2.f * fast_sig(2.f * x) - 1.f;
}

// ---------------------------------------------------------------
// Tiled fp32 GEMM, f32x2 inner product, DOUBLE-BUFFERED smem pipeline.
// C[m][n] = sum_k A[rowmap(m)][k] * W[n][k] + ba[n] (+ bb[n])
// Tiles 128x128x16, 256 threads, 8x8 micro-tile (row-pair packed).
// smem 2 stages x (As 8448 B + Ws 8448 B) = 33,792 B (static).
// ---------------------------------------------------------------
__global__ __launch_bounds__(256, 2)
void gemm_kernel(const float* __restrict__ A, const float* __restrict__ W,
                 const float* __restrict__ ba, const float* __restrict__ bb,
                 float* __restrict__ C, int M, int N, int K, int mapA)
{
    __shared__ float As[2][16][132];
    __shared__ float Ws[2][16][132];

    const int tid = threadIdx.x;
    const int bm  = blockIdx.y * 128;
    const int bn  = blockIdx.x * 128;
    const int tx  = tid & 15;
    const int ty  = tid >> 4;
    const int row0  = ty * 8;
    const int col0a = tx * 4;
    const int col0b = 64 + tx * 4;

    const int idx0 = tid * 2;
    const int idx1 = tid * 2 + 1;
    const int lrA0 = idx0 >> 2, kqA0 = idx0 & 3;
    const int lrA1 = idx1 >> 2, kqA1 = idx1 & 3;

    int m0 = bm + lrA0, m1 = bm + lrA1;
    long ar0 = mapA ? ((long)(m0 & 63) * SS + (m0 >> 6)) : (long)m0;
    long ar1 = mapA ? ((long)(m1 & 63) * SS + (m1 >> 6)) : (long)m1;
    const float* Ap0 = A + ar0 * K;
    const float* Ap1 = A + ar1 * K;
    const float* Wp0 = W + (long)(bn + lrA0) * K;
    const float* Wp1 = W + (long)(bn + lrA1) * K;

    u64 acc2[4][8];
#pragma unroll
    for (int i = 0; i < 4; i++)
#pragma unroll
        for (int j = 0; j < 8; j++) acc2[i][j] = 0ull;

    const int nk = K >> 4;

    // ---- prologue: load stage 0 ----
    float4 av0 = *(const float4*)(Ap0 + kqA0 * 4);
    float4 av1 = *(const float4*)(Ap1 + kqA1 * 4);
    float4 wv0 = *(const float4*)(Wp0 + kqA0 * 4);
    float4 wv1 = *(const float4*)(Wp1 + kqA1 * 4);
    {
        As[0][kqA0*4+0][lrA0] = av0.x; As[0][kqA0*4+1][lrA0] = av0.y;
        As[0][kqA0*4+2][lrA0] = av0.z; As[0][kqA0*4+3][lrA0] = av0.w;
        As[0][kqA1*4+0][lrA1] = av1.x; As[0][kqA1*4+1][lrA1] = av1.y;
        As[0][kqA1*4+2][lrA1] = av1.z; As[0][kqA1*4+3][lrA1] = av1.w;
        Ws[0][kqA0*4+0][lrA0] = wv0.x; Ws[0][kqA0*4+1][lrA0] = wv0.y;
        Ws[0][kqA0*4+2][lrA0] = wv0.z; Ws[0][kqA0*4+3][lrA0] = wv0.w;
        Ws[0][kqA1*4+0][lrA1] = wv1.x; Ws[0][kqA1*4+1][lrA1] = wv1.y;
        Ws[0][kqA1*4+2][lrA1] = wv1.z; Ws[0][kqA1*4+3][lrA1] = wv1.w;
    }
    __syncthreads();

    for (int kt = 0; kt < nk; kt++) {
        const int cur = kt & 1;
        const int nxt = cur ^ 1;
        const bool more = (kt + 1) < nk;

        // issue next tile's global loads early (latency hidden under compute)
        if (more) {
            int k0 = (kt + 1) << 4;
            av0 = *(const float4*)(Ap0 + k0 + kqA0 * 4);
            av1 = *(const float4*)(Ap1 + k0 + kqA1 * 4);
            wv0 = *(const float4*)(Wp0 + k0 + kqA0 * 4);
            wv1 = *(const float4*)(Wp1 + k0 + kqA1 * 4);
        }

        // compute on current buffer
#pragma unroll
        for (int k = 0; k < 16; k++) {
            ulonglong2 a01 = *(const ulonglong2*)&As[cur][k][row0];
            ulonglong2 a23 = *(const ulonglong2*)&As[cur][k][row0 + 4];
            float4 bA = *(const float4*)&Ws[cur][k][col0a];
            float4 bB = *(const float4*)&Ws[cur][k][col0b];
            u64 a2[4] = {a01.x, a01.y, a23.x, a23.y};
            u64 w2[8];
            w2[0] = splat2(bA.x); w2[1] = splat2(bA.y);
            w2[2] = splat2(bA.z); w2[3] = splat2(bA.w);
            w2[4] = splat2(bB.x); w2[5] = splat2(bB.y);
            w2[6] = splat2(bB.z); w2[7] = splat2(bB.w);
#pragma unroll
            for (int i = 0; i < 4; i++)
#pragma unroll
                for (int j = 0; j < 8; j++)
                    fma2(acc2[i][j], a2[i], w2[j]);
        }

        // stage next tile into the idle buffer
        if (more) {
            As[nxt][kqA0*4+0][lrA0] = av0.x; As[nxt][kqA0*4+1][lrA0] = av0.y;
            As[nxt][kqA0*4+2][lrA0] = av0.z; As[nxt][kqA0*4+3][lrA0] = av0.w;
            As[nxt][kqA1*4+0][lrA1] = av1.x; As[nxt][kqA1*4+1][lrA1] = av1.y;
            As[nxt][kqA1*4+2][lrA1] = av1.z; As[nxt][kqA1*4+3][lrA1] = av1.w;
            Ws[nxt][kqA0*4+0][lrA0] = wv0.x; Ws[nxt][kqA0*4+1][lrA0] = wv0.y;
            Ws[nxt][kqA0*4+2][lrA0] = wv0.z; Ws[nxt][kqA0*4+3][lrA0] = wv0.w;
            Ws[nxt][kqA1*4+0][lrA1] = wv1.x; Ws[nxt][kqA1*4+1][lrA1] = wv1.y;
            Ws[nxt][kqA1*4+2][lrA1] = wv1.z; Ws[nxt][kqA1*4+3][lrA1] = wv1.w;
            __syncthreads();
        }
    }

    float biasA[4], biasB[4];
#pragma unroll
    for (int j = 0; j < 4; j++) {
        int na = bn + col0a + j, nb = bn + col0b + j;
        biasA[j] = ba[na] + (bb ? bb[na] : 0.f);
        biasB[j] = ba[nb] + (bb ? bb[nb] : 0.f);
    }
#pragma unroll
    for (int i = 0; i < 4; i++) {
        long mA = bm + row0 + 2 * i;
        long mB = mA + 1;
        float2 u[8];
#pragma unroll
        for (int j = 0; j < 8; j++) u[j] = unpack2(acc2[i][j]);
        float4 oA0 = {u[0].x + biasA[0], u[1].x + biasA[1], u[2].x + biasA[2], u[3].x + biasA[3]};
        float4 oA1 = {u[4].x + biasB[0], u[5].x + biasB[1], u[6].x + biasB[2], u[7].x + biasB[3]};
        float4 oB0 = {u[0].y + biasA[0], u[1].y + biasA[1], u[2].y + biasA[2], u[3].y + biasA[3]};
        float4 oB1 = {u[4].y + biasB[0], u[5].y + biasB[1], u[6].y + biasB[2], u[7].y + biasB[3]};
        *(float4*)&C[mA * N + bn + col0a] = oA0;
        *(float4*)&C[mA * N + bn + col0b] = oA1;
        *(float4*)&C[mB * N + bn + col0a] = oB0;
        *(float4*)&C[mB * N + bn + col0b] = oB1;
    }
}

// ---------------------------------------------------------------
// Persistent LSTM layer kernel (unchanged from round 6).
// ---------------------------------------------------------------
__global__ __launch_bounds__(256, 1)
void lstm_layer_kernel(const float* __restrict__ xg,    // [S][64][4096]
                       const float* __restrict__ Whh,   // [4096][1024]
                       float* __restrict__ h,           // [2][64][1024]
                       float* __restrict__ y,           // [B][S][H]
                       float* __restrict__ out_h,
                       float* __restrict__ out_c)
{
    extern __shared__ float smem[];
    float* Wall = smem;                          // 32*1024 floats, swizzled
    float* HsF  = smem + 32 * 1024;              // 64 rows * 33 float4
    float* Pm   = HsF + 64 * 132;                // 64*33
    float* Cs   = Pm + 64 * 33;                  // 512

    float4*     Hs4 = (float4*)HsF;
    ulonglong2* HsU = (ulonglong2*)HsF;

    const int tid = threadIdx.x;
    const int j0  = blockIdx.x * 8;
    const int tx  = tid & 15;
    const int ty  = tid >> 4;
    const int c0  = tx * 2;
    const int r0  = ty * 4;
    const int swz = tx & 7;

    int soff[8];
    int sslot[8];
#pragma unroll
    for (int i = 0; i < 8; i++) {
        int idx = i * 256 + tid;
        int row = idx >> 5, kc = idx & 31;
        soff[i]  = row * HH + kc * 4;
        sslot[i] = row * 33 + kc;
    }

    {
        float4 z = make_float4(0.f, 0.f, 0.f, 0.f);
        *(float4*)&h[blockIdx.x * 1024 + tid * 4] = z;
        Cs[tid]       = 0.f;
        Cs[tid + 256] = 0.f;
    }
#pragma unroll 4
    for (int i = 0; i < 32; i++) {
        int idx = i * 256 + tid;
        int wr = idx >> 8;
        int kq = idx & 255;
        int grow = (wr >> 3) * HH + j0 + (wr & 7);
        float4 v = *(const float4*)(Whh + (long)grow * HH + kq * 4);
        int slot = kq ^ ((wr >> 1) & 7);
        *(float4*)&Wall[wr * 1024 + slot * 4] = v;
    }

    unsigned nbar = 0;
    __syncthreads();
    nbar++;
    if (tid == 0) {
        __threadfence();
        atomicAdd(&g_bar, 1u);
        while (*(volatile unsigned*)&g_bar < nbar * NBLK) { }
    }
    __syncthreads();

    const ulonglong2* Wp0 = (const ulonglong2*)&Wall[c0 * 1024];
    const ulonglong2* Wp1 = (const ulonglong2*)&Wall[(c0 + 1) * 1024];

    for (int t = 0; t < SS; t++) {
        const float* h_in  = h + (size_t)(t & 1) * BH;
        float*       h_out = h + (size_t)((t + 1) & 1) * BH;
        const float* xg_t  = xg + (size_t)t * BB * G4;

        const int gate = c0 >> 3;
        const int jl0  = c0 & 7;
        float2 xv[4];
#pragma unroll
        for (int r = 0; r < 4; r++)
            xv[r] = *(const float2*)(xg_t + (long)(r0 + r) * G4 + gate * HH + j0 + jl0);

        u64 acc[4][2];
#pragma unroll
        for (int r = 0; r < 4; r++) { acc[r][0] = 0ull; acc[r][1] = 0ull; }

        float4 pf[8];
#pragma unroll
        for (int i = 0; i < 8; i++)
            pf[i] = __ldcg((const float4*)(h_in + soff[i]));

#pragma unroll 1
        for (int cc = 0; cc < 8; cc++) {
            __syncthreads();
#pragma unroll
            for (int i = 0; i < 8; i++) Hs4[sslot[i]] = pf[i];
            __syncthreads();
            if (cc < 7) {
#pragma unroll
                for (int i = 0; i < 8; i++)
                    pf[i] = __ldcg((const float4*)(h_in + soff[i] + (cc + 1) * 128));
            }

            const int kqb = cc * 32;
#pragma unroll 4
            for (int kql = 0; kql < 32; kql++) {
                int s = (kqb + kql) ^ swz;
                ulonglong2 w0 = Wp0[s];
                ulonglong2 w1 = Wp1[s];
#pragma unroll
                for (int r = 0; r < 4; r++) {
                    ulonglong2 hv = HsU[(r0 + r) * 33 + kql];
                    fma2(acc[r][0], hv.x, w0.x);
                    fma2(acc[r][0], hv.y, w0.y);
                    fma2(acc[r][1], hv.x, w1.x);
                    fma2(acc[r][1], hv.y, w1.y);
                }
            }
        }

#pragma unroll
        for (int r = 0; r < 4; r++) {
            int b = r0 + r;
            float2 u0 = unpack2(acc[r][0]);
            float2 u1 = unpack2(acc[r][1]);
            Pm[b * 33 + c0]     = u0.x + u0.y + xv[r].x;
            Pm[b * 33 + c0 + 1] = u1.x + u1.y + xv[r].y;
        }
        __syncthreads();

#pragma unroll
        for (int pi = 0; pi < 2; pi++) {
            int p  = tid + pi * 256;
            int b  = p >> 3;
            int jl = p & 7;
            int j  = j0 + jl;
            float iv = fast_sig (Pm[b * 33 + 0  + jl]);
            float fv = fast_sig (Pm[b * 33 + 8  + jl]);
            float gv = fast_tanh(Pm[b * 33 + 16 + jl]);
            float ov = fast_sig (Pm[b * 33 + 24 + jl]);
            float cn = fv * Cs[b * 8 + jl] + iv * gv;
            Cs[b * 8 + jl] = cn;
            float hn = ov * fast_tanh(cn);
            __stcg(h_out + (long)b * HH + j, hn);
            y[((long)b * SS + t) * HH + j] = hn;
            if (t == SS - 1) {
                out_h[(long)b * HH + j] = hn;
                out_c[(long)b * HH + j] = cn;
            }
        }

        __threadfence();
        __syncthreads();
        nbar++;
        if (tid == 0) {
            atomicAdd(&g_bar, 1u);
            while (*(volatile unsigned*)&g_bar < nbar * NBLK) { }
            __threadfence();
        }
        __syncthreads();
    }
}

extern "C" void kernel_launch(void* const* d_in, const int* in_sizes, int n_in,
                              void* d_out, int out_size)
{
    const float* x     = (const float*)d_in[0];
    const float* W_ih0 = (const float*)d_in[1];
    const float* W_hh0 = (const float*)d_in[2];
    const float* b_ih0 = (const float*)d_in[3];
    const float* b_hh0 = (const float*)d_in[4];
    const float* W_ih1 = (const float*)d_in[5];
    const float* W_hh1 = (const float*)d_in[6];
    const float* b_ih1 = (const float*)d_in[7];
    const float* b_hh1 = (const float*)d_in[8];
    const float* W_fc  = (const float*)d_in[9];
    const float* b_fc  = (const float*)d_in[10];
    float* out = (float*)d_out;

    float *xg, *y, *h;
    unsigned* bar;
    cudaGetSymbolAddress((void**)&xg,  g_xg);
    cudaGetSymbolAddress((void**)&y,   g_y);
    cudaGetSymbolAddress((void**)&h,   g_h);
    cudaGetSymbolAddress((void**)&bar, g_bar);

    const int SMEM_LAYER = (32 * 1024 + 64 * 132 + 64 * 33 + 512) * 4;  // 175,360
    cudaFuncSetAttribute(lstm_layer_kernel,
                         cudaFuncAttributeMaxDynamicSharedMemorySize, SMEM_LAYER);

    const int M = SS * BB;  // 32768

    // ---------------- layer 0 ----------------
    gemm_kernel<<<dim3(G4 / 128, M / 128), 256>>>(
        x, W_ih0, b_ih0, b_hh0, xg, M, G4, II, 1);
    cudaMemsetAsync(bar, 0, sizeof(unsigned));
    lstm_layer_kernel<<<NBLK, 256, SMEM_LAYER>>>(
        xg, W_hh0, h, y,
        out + OUT_ELEMS,
        out + OUT_ELEMS + 2 * BH);

    // ---------------- layer 1 ----------------
    gemm_kernel<<<dim3(G4 / 128, M / 128), 256>>>(
        y, W_ih1, b_ih1, b_hh1, xg, M, G4, HH, 1);
    cudaMemsetAsync(bar, 0, sizeof(unsigned));
    lstm_layer_kernel<<<NBLK, 256, SMEM_LAYER>>>(
        xg, W_hh1, h, y,
        out + OUT_ELEMS + BH,
        out + OUT_ELEMS + 3 * BH);

    // ---------------- FC ----------------
    gemm_kernel<<<dim3(OO / 128, M / 128), 256>>>(
        y, W_fc, b_fc, nullptr, out, M, OO, HH, 0);
}